// round 2
// baseline (speedup 1.0000x reference)
#include <cuda_runtime.h>
#include <cuda_fp16.h>
#include <stdint.h>

// Problem dims
#define BB   64
#define TT   4096
#define NTOK (BB*TT)          // 262144
#define NTILES 2048           // NTOK/128

// smem strides (halves), chosen conflict-free
#define SC 104                // comb stride (K=96 padded)
#define SH 136                // hidden/weight stride (K=128 padded)

// ---------------- device scratch (statically allocated, allowed) ----------------
__device__ __align__(16) __half g_wT[(size_t)BB * 64 * 64 * 64]; // [b][y][x][c] fp16, 32MB
__device__ __align__(16) __half g_wts[4 * 4 * 128 * 128];        // [net][layer][n][k] fp16
__device__ float g_bias[4 * 4 * 128];                            // [net][layer][n]
__device__ float g_part[2][NTILES];                              // per-tile s-sums

// ---------------- mma helper ----------------
__device__ __forceinline__ void mma16816(float c[4], const unsigned a[4],
                                         unsigned b0, unsigned b1) {
    asm volatile(
        "mma.sync.aligned.m16n8k16.row.col.f32.f16.f16.f32 "
        "{%0,%1,%2,%3}, {%4,%5,%6,%7}, {%8,%9}, {%0,%1,%2,%3};"
        : "+f"(c[0]), "+f"(c[1]), "+f"(c[2]), "+f"(c[3])
        : "r"(a[0]), "r"(a[1]), "r"(a[2]), "r"(a[3]), "r"(b0), "r"(b1));
}

// ---------------- transpose w[B,C,H,W] f32 -> wT[b][y][x][c] fp16 ----------------
__global__ void k_transpose(const float* __restrict__ w) {
    __shared__ float tile[64][65];
    int bid = blockIdx.x;              // 4096 blocks = (b, y)
    int b = bid >> 6, y = bid & 63;
    int t = threadIdx.x;
    {
        int c = t >> 2, xq = (t & 3) * 16;
        const float4* src = (const float4*)(w + ((((b << 6) | c) << 6 | y) << 6) + xq);
#pragma unroll
        for (int j = 0; j < 4; j++) {
            float4 v = src[j];
            tile[c][xq + 4 * j + 0] = v.x;
            tile[c][xq + 4 * j + 1] = v.y;
            tile[c][xq + 4 * j + 2] = v.z;
            tile[c][xq + 4 * j + 3] = v.w;
        }
    }
    __syncthreads();
    {
        int xx = t >> 2, cq = (t & 3) * 16;
        __half2* dst = (__half2*)(g_wT + ((((size_t)(((b << 6) | y)) << 6 | xx)) << 6) + cq);
#pragma unroll
        for (int j = 0; j < 8; j++)
            dst[j] = __floats2half2_rn(tile[cq + 2 * j][xx], tile[cq + 2 * j + 1][xx]);
    }
}

// ---------------- pack weights (permuted cols: [lf 0..63 | cond 64..79 | z 80 | 0]) ----------------
__global__ void k_pack(const float* __restrict__ W0, const float* __restrict__ b0,
                       const float* __restrict__ W1, const float* __restrict__ b1) {
    int idx = blockIdx.x * 256 + threadIdx.x;      // 262144 total
    int net = idx >> 16;
    int rem = idx & 65535;
    int layer = rem >> 14;
    int rem2 = rem & 16383;
    int n = rem2 >> 7, k = rem2 & 127;
    float v = 0.f;
    if (layer == 0) {
        int oc = -1;
        if (k < 64) oc = 1 + k;                    // lf -> orig cols 1..64
        else if (k < 80) oc = 65 + (k - 64);       // cond -> orig cols 65..80
        else if (k == 80) oc = 0;                  // z_keep -> orig col 0
        if (oc >= 0) v = W0[(net * 128 + n) * 81 + oc];
    } else {
        v = W1[((net * 3 + (layer - 1)) * 128 + n) * 128 + k];
    }
    g_wts[idx] = __float2half_rn(v);
    if (idx < 2048) {
        int bn = idx >> 9, bl = (idx >> 7) & 3, bb_ = idx & 127;
        g_bias[idx] = (bl == 0) ? b0[bn * 128 + bb_]
                                : b1[((bn * 3 + bl - 1) * 128) + bb_];
    }
}

// ---------------- fused coupling pass ----------------
template <int PASS>
__global__ void __launch_bounds__(256, 2) k_pass(
    const float* __restrict__ x, const float* __restrict__ cond,
    const float* __restrict__ W2, const float* __restrict__ b2,
    float* __restrict__ out) {
    extern __shared__ __half smbase[];
    __half* combS = smbase;                 // 128 x SC
    __half* hS    = combS + 128 * SC;       // 128 x SH (in-place hidden)
    __half* wS    = hS + 128 * SH;          // 128 x SH (weights)
    float*  sbias = (float*)(wS + 128 * SH);
    float*  w2s   = sbias + 128;
    float*  sraw  = w2s + 128;
    float*  traw  = sraw + 128;
    float*  sred  = traw + 128;

    int tid = threadIdx.x;
    int tile = blockIdx.x;

    // ===== gather + build comb =====
    {
        int tk = tid >> 1, p = tid & 1;
        int g0 = tile * 128 + tk;
        int b = g0 >> 12;
        float zy = __ldg(&x[g0 * 2 + 1]);
        float zx = (PASS == 0) ? __ldg(&x[g0 * 2]) : out[g0 * 2];
        float zkeep = (PASS == 0) ? zy : zx;
        float ix = zx * 63.f, iy = zy * 63.f;
        float ix0 = floorf(ix), iy0 = floorf(iy);
        float wx1 = ix - ix0, wx0 = 1.f - wx1;
        float wy1 = iy - iy0, wy0 = 1.f - wy1;
        float acc[32];
#pragma unroll
        for (int i = 0; i < 32; i++) acc[i] = 0.f;
        float cxs[4] = {ix0, ix0 + 1.f, ix0, ix0 + 1.f};
        float cys[4] = {iy0, iy0, iy0 + 1.f, iy0 + 1.f};
        float cws[4] = {wy0 * wx0, wy0 * wx1, wy1 * wx0, wy1 * wx1};
#pragma unroll
        for (int cr = 0; cr < 4; cr++) {
            float xf = cxs[cr], yf = cys[cr], wt = cws[cr];
            if (xf >= 0.f && xf <= 63.f && yf >= 0.f && yf <= 63.f) {
                int xi = (int)xf, yi = (int)yf;
                const __half2* src = (const __half2*)(
                    g_wT + ((((size_t)((b << 6) | yi) << 6 | xi)) << 6) + (p << 5));
#pragma unroll
                for (int j = 0; j < 16; j++) {
                    float2 f = __half22float2(src[j]);
                    acc[2 * j]     += wt * f.x;
                    acc[2 * j + 1] += wt * f.y;
                }
            }
        }
        __half* crow = combS + tk * SC;
        __half2* dst = (__half2*)(crow + p * 32);
#pragma unroll
        for (int j = 0; j < 16; j++) dst[j] = __floats2half2_rn(acc[2 * j], acc[2 * j + 1]);
        if (p == 0) {
#pragma unroll
            for (int i = 0; i < 16; i++)
                crow[64 + i] = __float2half_rn(__ldg(&cond[b * 16 + i]));
            crow[80] = __float2half_rn(zkeep);
#pragma unroll
            for (int cc = 81; cc < 88; cc++) crow[cc] = __float2half_rn(0.f);
        } else {
#pragma unroll
            for (int cc = 88; cc < 96; cc++) crow[cc] = __float2half_rn(0.f);
        }
    }

    int wid = tid >> 5, lane = tid & 31;
    int gid = lane >> 2, tig = lane & 3;
    int warpM = (wid & 3) * 32;
    int warpN = (wid >> 2) * 64;

    // ===== two MLPs (s-net then t-net) =====
    for (int ni = 0; ni < 2; ni++) {
        int net = PASS * 2 + ni;
        for (int layer = 0; layer < 4; layer++) {
            // stage weights + bias into smem
            const __half* gw = g_wts + ((net * 4 + layer) << 14);
#pragma unroll
            for (int i = 0; i < 8; i++) {
                int ci = tid + i * 256;
                int n = ci >> 4, koff = (ci & 15) * 8;
                *(int4*)(wS + n * SH + koff) = *(const int4*)(gw + n * 128 + koff);
            }
            if (tid < 128) sbias[tid] = g_bias[(net * 4 + layer) * 128 + tid];
            __syncthreads();

            const __half* A = (layer == 0) ? combS : hS;
            int sa = (layer == 0) ? SC : SH;
            int ksteps = (layer == 0) ? 6 : 8;

            float acc[2][8][4];
#pragma unroll
            for (int mt = 0; mt < 2; mt++)
#pragma unroll
                for (int nt = 0; nt < 8; nt++)
#pragma unroll
                    for (int q = 0; q < 4; q++) acc[mt][nt][q] = 0.f;

            for (int ks = 0; ks < ksteps; ks++) {
                int k0 = ks * 16;
                unsigned af[2][4];
#pragma unroll
                for (int mt = 0; mt < 2; mt++) {
                    const __half* ap = A + (warpM + mt * 16 + gid) * sa + k0 + tig * 2;
                    af[mt][0] = *(const unsigned*)ap;
                    af[mt][1] = *(const unsigned*)(ap + 8 * sa);
                    af[mt][2] = *(const unsigned*)(ap + 8);
                    af[mt][3] = *(const unsigned*)(ap + 8 * sa + 8);
                }
#pragma unroll
                for (int nt = 0; nt < 8; nt++) {
                    const __half* bp = wS + (warpN + nt * 8 + gid) * SH + k0 + tig * 2;
                    unsigned b0r = *(const unsigned*)bp;
                    unsigned b1r = *(const unsigned*)(bp + 8);
                    mma16816(acc[0][nt], af[0], b0r, b1r);
                    mma16816(acc[1][nt], af[1], b0r, b1r);
                }
            }
            __syncthreads();   // all reads of A/W done before in-place writes

            // epilogue: bias + silu -> hS (fp16)
#pragma unroll
            for (int mt = 0; mt < 2; mt++) {
#pragma unroll
                for (int nt = 0; nt < 8; nt++) {
                    int r = warpM + mt * 16 + gid;
                    int c = warpN + nt * 8 + tig * 2;
                    float b0v = sbias[c], b1v = sbias[c + 1];
                    float v0 = acc[mt][nt][0] + b0v;
                    float v1 = acc[mt][nt][1] + b1v;
                    float v2 = acc[mt][nt][2] + b0v;
                    float v3 = acc[mt][nt][3] + b1v;
                    v0 = v0 / (1.f + __expf(-v0));
                    v1 = v1 / (1.f + __expf(-v1));
                    v2 = v2 / (1.f + __expf(-v2));
                    v3 = v3 / (1.f + __expf(-v3));
                    *(__half2*)(hS + r * SH + c)       = __floats2half2_rn(v0, v1);
                    *(__half2*)(hS + (r + 8) * SH + c) = __floats2half2_rn(v2, v3);
                }
            }
            // next iteration's pre-gemm sync covers epilogue->read hazard
        }

        // final GEMV: out[t] = h[t,:] . W2[net] + b2[net]
        if (tid < 128) w2s[tid] = __ldg(&W2[net * 128 + tid]);
        __syncthreads();
        {
            int tk = tid >> 1, p = tid & 1;
            const __half2* hp = (const __half2*)(hS + tk * SH + p * 64);
            float sum = 0.f;
#pragma unroll
            for (int j = 0; j < 32; j++) {
                float2 f = __half22float2(hp[j]);
                sum += f.x * w2s[p * 64 + 2 * j] + f.y * w2s[p * 64 + 2 * j + 1];
            }
            sum += __shfl_xor_sync(0xffffffffu, sum, 1);
            if (p == 0) {
                float r = sum + __ldg(&b2[net]);
                if (ni == 0) sraw[tk] = r; else traw[tk] = r;
            }
        }
        __syncthreads();
    }

    // ===== coupling epilogue + deterministic block reduce of s =====
    if (tid < 128) {
        int g0 = tile * 128 + tid;
        float zold = (PASS == 0) ? __ldg(&x[g0 * 2]) : __ldg(&x[g0 * 2 + 1]);
        float s = tanhf(sraw[tid]) * 1.5f;
        float z = zold * expf(s) + traw[tid];
        out[g0 * 2 + PASS] = z;
        sred[tid] = s;
    }
    __syncthreads();
    if (tid < 64) sred[tid] += sred[tid + 64];
    __syncthreads();
    if (tid < 32) {
        float v = sred[tid] + sred[tid + 32];
#pragma unroll
        for (int off = 16; off; off >>= 1) v += __shfl_xor_sync(0xffffffffu, v, off);
        if (tid == 0) g_part[PASS][tile] = v;
    }
}

// ---------------- log-det reduce ----------------
__global__ void k_reduce(float* __restrict__ out) {
    int b = threadIdx.x;
    if (b < BB) {
        float acc = 0.f;
        for (int i = 0; i < 32; i++)
            acc += g_part[0][b * 32 + i] + g_part[1][b * 32 + i];
        out[(size_t)NTOK * 2 + b] = acc;
    }
}

// ---------------- launcher ----------------
extern "C" void kernel_launch(void* const* d_in, const int* in_sizes, int n_in,
                              void* d_out, int out_size) {
    const float* x    = (const float*)d_in[0];
    const float* w    = (const float*)d_in[1];
    const float* cond = (const float*)d_in[2];
    const float* W0   = (const float*)d_in[3];
    const float* b0   = (const float*)d_in[4];
    const float* W1   = (const float*)d_in[5];
    const float* b1   = (const float*)d_in[6];
    const float* W2   = (const float*)d_in[7];
    const float* b2   = (const float*)d_in[8];
    float* out = (float*)d_out;

    const int SMEM = (128 * SC + 128 * SH + 128 * SH) * 2 + 5 * 128 * 4; // 98816
    cudaFuncSetAttribute(k_pass<0>, cudaFuncAttributeMaxDynamicSharedMemorySize, SMEM);
    cudaFuncSetAttribute(k_pass<1>, cudaFuncAttributeMaxDynamicSharedMemorySize, SMEM);

    k_transpose<<<4096, 256>>>(w);
    k_pack<<<1024, 256>>>(W0, b0, W1, b1);
    k_pass<0><<<NTILES, 256, SMEM>>>(x, cond, W2, b2, out);
    k_pass<1><<<NTILES, 256, SMEM>>>(x, cond, W2, b2, out);
    k_reduce<<<1, 64>>>(out);
}

// round 3
// speedup vs baseline: 1.6580x; 1.6580x over previous
#include <cuda_runtime.h>
#include <cuda_fp16.h>
#include <stdint.h>

// Problem dims
#define BB   64
#define TT   4096
#define NTOK (BB*TT)          // 262144
#define NTILES 2048           // NTOK/128

// smem strides (halves), chosen conflict-free
#define SC 104                // comb stride (K=96 padded), 208B row
#define SH 136                // hidden/weight stride (K=128 padded), 272B row

// ---------------- device scratch ----------------
__device__ __align__(16) __half g_wT[(size_t)BB * 64 * 64 * 64]; // [b][y][x][c] fp16, 32MB
__device__ __align__(16) __half g_wts[4 * 4 * 128 * 128];        // [net][layer][n][k] fp16
__device__ float g_bias[4 * 4 * 128];                            // [net][layer][n]
__device__ float g_part[2][NTILES];                              // per-tile s-sums

// ---------------- helpers ----------------
__device__ __forceinline__ void mma16816(float c[4], const unsigned a[4],
                                         unsigned b0, unsigned b1) {
    asm volatile(
        "mma.sync.aligned.m16n8k16.row.col.f32.f16.f16.f32 "
        "{%0,%1,%2,%3}, {%4,%5,%6,%7}, {%8,%9}, {%0,%1,%2,%3};"
        : "+f"(c[0]), "+f"(c[1]), "+f"(c[2]), "+f"(c[3])
        : "r"(a[0]), "r"(a[1]), "r"(a[2]), "r"(a[3]), "r"(b0), "r"(b1));
}

__device__ __forceinline__ void ldsm_x4(unsigned r[4], uint32_t addr) {
    asm volatile("ldmatrix.sync.aligned.m8n8.x4.shared.b16 {%0,%1,%2,%3}, [%4];"
                 : "=r"(r[0]), "=r"(r[1]), "=r"(r[2]), "=r"(r[3]) : "r"(addr));
}

__device__ __forceinline__ uint32_t smem_u32(const void* p) {
    uint32_t a;
    asm("{ .reg .u64 t; cvta.to.shared.u64 t, %1; cvt.u32.u64 %0, t; }" : "=r"(a) : "l"(p));
    return a;
}

// silu with cheap MUFU ops: v * 1/(1+exp(-v)); exp via ex2, recip via rcp.approx
__device__ __forceinline__ float fast_silu(float v) {
    float e, r;
    asm("ex2.approx.ftz.f32 %0, %1;" : "=f"(e) : "f"(-1.442695041f * v));
    asm("rcp.approx.ftz.f32 %0, %1;" : "=f"(r) : "f"(1.0f + e));
    return v * r;
}

// ---------------- transpose w[B,C,H,W] f32 -> wT[b][y][x][c] fp16 ----------------
__global__ void k_transpose(const float* __restrict__ w) {
    __shared__ float tile[64][65];
    int bid = blockIdx.x;              // 4096 blocks = (b, y)
    int b = bid >> 6, y = bid & 63;
    int t = threadIdx.x;
    {
        int c = t >> 2, xq = (t & 3) * 16;
        const float4* src = (const float4*)(w + ((((b << 6) | c) << 6 | y) << 6) + xq);
#pragma unroll
        for (int j = 0; j < 4; j++) {
            float4 v = src[j];
            tile[c][xq + 4 * j + 0] = v.x;
            tile[c][xq + 4 * j + 1] = v.y;
            tile[c][xq + 4 * j + 2] = v.z;
            tile[c][xq + 4 * j + 3] = v.w;
        }
    }
    __syncthreads();
    {
        int xx = t >> 2, cq = (t & 3) * 16;
        __half2* dst = (__half2*)(g_wT + ((((size_t)(((b << 6) | y)) << 6 | xx)) << 6) + cq);
#pragma unroll
        for (int j = 0; j < 8; j++)
            dst[j] = __floats2half2_rn(tile[cq + 2 * j][xx], tile[cq + 2 * j + 1][xx]);
    }
}

// ---------------- pack weights (permuted cols: [lf 0..63 | cond 64..79 | z 80 | 0]) ----------------
__global__ void k_pack(const float* __restrict__ W0, const float* __restrict__ b0,
                       const float* __restrict__ W1, const float* __restrict__ b1) {
    int idx = blockIdx.x * 256 + threadIdx.x;      // 262144 total
    int net = idx >> 16;
    int rem = idx & 65535;
    int layer = rem >> 14;
    int rem2 = rem & 16383;
    int n = rem2 >> 7, k = rem2 & 127;
    float v = 0.f;
    if (layer == 0) {
        int oc = -1;
        if (k < 64) oc = 1 + k;                    // lf -> orig cols 1..64
        else if (k < 80) oc = 65 + (k - 64);       // cond -> orig cols 65..80
        else if (k == 80) oc = 0;                  // z_keep -> orig col 0
        if (oc >= 0) v = W0[(net * 128 + n) * 81 + oc];
    } else {
        v = W1[((net * 3 + (layer - 1)) * 128 + n) * 128 + k];
    }
    g_wts[idx] = __float2half_rn(v);
    if (idx < 2048) {
        int bn = idx >> 9, bl = (idx >> 7) & 3, bb_ = idx & 127;
        g_bias[idx] = (bl == 0) ? b0[bn * 128 + bb_]
                                : b1[((bn * 3 + bl - 1) * 128) + bb_];
    }
}

// ---------------- fused coupling pass ----------------
template <int PASS>
__global__ void __launch_bounds__(256, 2) k_pass(
    const float* __restrict__ x, const float* __restrict__ cond,
    const float* __restrict__ W2, const float* __restrict__ b2,
    float* __restrict__ out) {
    extern __shared__ __half smbase[];
    __half* combS = smbase;                 // 128 x SC
    __half* hS    = combS + 128 * SC;       // 128 x SH (in-place hidden)
    __half* wS    = hS + 128 * SH;          // 128 x SH (weights)
    float*  sbias = (float*)(wS + 128 * SH);
    float*  w2s   = sbias + 128;
    float*  sraw  = w2s + 128;
    float*  traw  = sraw + 128;
    float*  sred  = traw + 128;

    int tid = threadIdx.x;
    int tile = blockIdx.x;

    // ===== gather + build comb =====
    {
        int tk = tid >> 1, p = tid & 1;
        int g0 = tile * 128 + tk;
        int b = g0 >> 12;
        float zy = __ldg(&x[g0 * 2 + 1]);
        float zx = (PASS == 0) ? __ldg(&x[g0 * 2]) : out[g0 * 2];
        float zkeep = (PASS == 0) ? zy : zx;
        float ix = zx * 63.f, iy = zy * 63.f;
        float ix0 = floorf(ix), iy0 = floorf(iy);
        float wx1 = ix - ix0, wx0 = 1.f - wx1;
        float wy1 = iy - iy0, wy0 = 1.f - wy1;
        float acc[32];
#pragma unroll
        for (int i = 0; i < 32; i++) acc[i] = 0.f;
        float cxs[4] = {ix0, ix0 + 1.f, ix0, ix0 + 1.f};
        float cys[4] = {iy0, iy0, iy0 + 1.f, iy0 + 1.f};
        float cws[4] = {wy0 * wx0, wy0 * wx1, wy1 * wx0, wy1 * wx1};
#pragma unroll
        for (int cr = 0; cr < 4; cr++) {
            float xf = cxs[cr], yf = cys[cr], wt = cws[cr];
            if (xf >= 0.f && xf <= 63.f && yf >= 0.f && yf <= 63.f) {
                int xi = (int)xf, yi = (int)yf;
                const __half2* src = (const __half2*)(
                    g_wT + ((((size_t)((b << 6) | yi) << 6 | xi)) << 6) + (p << 5));
#pragma unroll
                for (int j = 0; j < 16; j++) {
                    float2 f = __half22float2(src[j]);
                    acc[2 * j]     += wt * f.x;
                    acc[2 * j + 1] += wt * f.y;
                }
            }
        }
        __half* crow = combS + tk * SC;
        __half2* dst = (__half2*)(crow + p * 32);
#pragma unroll
        for (int j = 0; j < 16; j++) dst[j] = __floats2half2_rn(acc[2 * j], acc[2 * j + 1]);
        if (p == 0) {
#pragma unroll
            for (int i = 0; i < 16; i++)
                crow[64 + i] = __float2half_rn(__ldg(&cond[b * 16 + i]));
            crow[80] = __float2half_rn(zkeep);
#pragma unroll
            for (int cc = 81; cc < 88; cc++) crow[cc] = __float2half_rn(0.f);
        } else {
#pragma unroll
            for (int cc = 88; cc < 96; cc++) crow[cc] = __float2half_rn(0.f);
        }
    }

    int wid = tid >> 5, lane = tid & 31;
    int gid = lane >> 2, tig = lane & 3;
    int warpM = (wid & 3) * 32;
    int warpN = (wid >> 2) * 64;

    // ldmatrix per-thread row/col offsets
    int aRow = lane & 15;                 // rows 0..15
    int aK   = (lane >> 4) * 8;           // 0 or 8 (halves)
    int bRow = (lane & 7) + ((lane >> 4) & 1) * 8;  // n-row within 16
    int bK   = ((lane >> 3) & 1) * 8;               // 0 or 8 (halves)

    uint32_t combA = smem_u32(combS);
    uint32_t hA    = smem_u32(hS);
    uint32_t wA    = smem_u32(wS);

    // ===== two MLPs (s-net then t-net) =====
    for (int ni = 0; ni < 2; ni++) {
        int net = PASS * 2 + ni;
        for (int layer = 0; layer < 4; layer++) {
            // stage weights + bias into smem
            const __half* gw = g_wts + ((net * 4 + layer) << 14);
#pragma unroll
            for (int i = 0; i < 8; i++) {
                int ci = tid + i * 256;
                int n = ci >> 4, koff = (ci & 15) * 8;
                *(int4*)(wS + n * SH + koff) = *(const int4*)(gw + n * 128 + koff);
            }
            if (tid < 128) sbias[tid] = g_bias[(net * 4 + layer) * 128 + tid];
            __syncthreads();

            uint32_t Aaddr = (layer == 0) ? combA : hA;
            int sa = (layer == 0) ? SC : SH;
            int ksteps = (layer == 0) ? 6 : 8;

            // per-thread ldmatrix base addresses (bytes)
            uint32_t a0 = Aaddr + ((warpM + aRow) * sa + aK) * 2;
            uint32_t a1 = Aaddr + ((warpM + 16 + aRow) * sa + aK) * 2;
            uint32_t bb = wA + ((warpN + bRow) * SH + bK) * 2;

            float acc[2][8][4];
#pragma unroll
            for (int mt = 0; mt < 2; mt++)
#pragma unroll
                for (int nt = 0; nt < 8; nt++)
#pragma unroll
                    for (int q = 0; q < 4; q++) acc[mt][nt][q] = 0.f;

            for (int ks = 0; ks < ksteps; ks++) {
                unsigned af[2][4];
                ldsm_x4(af[0], a0 + ks * 32);
                ldsm_x4(af[1], a1 + ks * 32);
#pragma unroll
                for (int ntp = 0; ntp < 4; ntp++) {
                    unsigned bf[4];
                    ldsm_x4(bf, bb + (ntp * 16 * SH) * 2 + ks * 32);
                    mma16816(acc[0][2 * ntp],     af[0], bf[0], bf[1]);
                    mma16816(acc[0][2 * ntp + 1], af[0], bf[2], bf[3]);
                    mma16816(acc[1][2 * ntp],     af[1], bf[0], bf[1]);
                    mma16816(acc[1][2 * ntp + 1], af[1], bf[2], bf[3]);
                }
            }
            __syncthreads();   // all reads of A/W done before in-place writes

            // epilogue: bias + silu -> hS (fp16)
#pragma unroll
            for (int mt = 0; mt < 2; mt++) {
#pragma unroll
                for (int nt = 0; nt < 8; nt++) {
                    int r = warpM + mt * 16 + gid;
                    int c = warpN + nt * 8 + tig * 2;
                    float b0v = sbias[c], b1v = sbias[c + 1];
                    float v0 = fast_silu(acc[mt][nt][0] + b0v);
                    float v1 = fast_silu(acc[mt][nt][1] + b1v);
                    float v2 = fast_silu(acc[mt][nt][2] + b0v);
                    float v3 = fast_silu(acc[mt][nt][3] + b1v);
                    *(__half2*)(hS + r * SH + c)       = __floats2half2_rn(v0, v1);
                    *(__half2*)(hS + (r + 8) * SH + c) = __floats2half2_rn(v2, v3);
                }
            }
            // next iteration's pre-gemm sync covers epilogue->read hazard
        }

        // final GEMV: out[t] = h[t,:] . W2[net] + b2[net]
        if (tid < 128) w2s[tid] = __ldg(&W2[net * 128 + tid]);
        __syncthreads();
        {
            int tk = tid >> 1, p = tid & 1;
            const __half2* hp = (const __half2*)(hS + tk * SH + p * 64);
            float sum = 0.f;
#pragma unroll
            for (int j = 0; j < 32; j++) {
                float2 f = __half22float2(hp[j]);
                sum += f.x * w2s[p * 64 + 2 * j] + f.y * w2s[p * 64 + 2 * j + 1];
            }
            sum += __shfl_xor_sync(0xffffffffu, sum, 1);
            if (p == 0) {
                float r = sum + __ldg(&b2[net]);
                if (ni == 0) sraw[tk] = r; else traw[tk] = r;
            }
        }
        __syncthreads();
    }

    // ===== coupling epilogue + deterministic block reduce of s =====
    if (tid < 128) {
        int g0 = tile * 128 + tid;
        float zold = (PASS == 0) ? __ldg(&x[g0 * 2]) : __ldg(&x[g0 * 2 + 1]);
        float s = tanhf(sraw[tid]) * 1.5f;
        float z = zold * __expf(s) + traw[tid];
        out[g0 * 2 + PASS] = z;
        sred[tid] = s;
    }
    __syncthreads();
    if (tid < 64) sred[tid] += sred[tid + 64];
    __syncthreads();
    if (tid < 32) {
        float v = sred[tid] + sred[tid + 32];
#pragma unroll
        for (int off = 16; off; off >>= 1) v += __shfl_xor_sync(0xffffffffu, v, off);
        if (tid == 0) g_part[PASS][tile] = v;
    }
}

// ---------------- log-det reduce ----------------
__global__ void k_reduce(float* __restrict__ out) {
    int b = threadIdx.x;
    if (b < BB) {
        float acc = 0.f;
        for (int i = 0; i < 32; i++)
            acc += g_part[0][b * 32 + i] + g_part[1][b * 32 + i];
        out[(size_t)NTOK * 2 + b] = acc;
    }
}

// ---------------- launcher ----------------
extern "C" void kernel_launch(void* const* d_in, const int* in_sizes, int n_in,
                              void* d_out, int out_size) {
    const float* x    = (const float*)d_in[0];
    const float* w    = (const float*)d_in[1];
    const float* cond = (const float*)d_in[2];
    const float* W0   = (const float*)d_in[3];
    const float* b0   = (const float*)d_in[4];
    const float* W1   = (const float*)d_in[5];
    const float* b1   = (const float*)d_in[6];
    const float* W2   = (const float*)d_in[7];
    const float* b2   = (const float*)d_in[8];
    float* out = (float*)d_out;

    const int SMEM = (128 * SC + 128 * SH + 128 * SH) * 2 + 5 * 128 * 4; // 98816
    cudaFuncSetAttribute(k_pass<0>, cudaFuncAttributeMaxDynamicSharedMemorySize, SMEM);
    cudaFuncSetAttribute(k_pass<1>, cudaFuncAttributeMaxDynamicSharedMemorySize, SMEM);

    k_transpose<<<4096, 256>>>(w);
    k_pack<<<1024, 256>>>(W0, b0, W1, b1);
    k_pass<0><<<NTILES, 256, SMEM>>>(x, cond, W2, b2, out);
    k_pass<1><<<NTILES, 256, SMEM>>>(x, cond, W2, b2, out);
    k_reduce<<<1, 64>>>(out);
}